// round 1
// baseline (speedup 1.0000x reference)
#include <cuda_runtime.h>

#define NN 4096
#define FF 128
#define EE 64
#define MAXD 192
#define LRALPHA 0.2f

// ---- scratch (device globals; no allocation allowed) ----
__device__ float g_wa[6][FF];          // W@a projected vectors: (fwd a1,a2),(bwd a1,a2),(geo a1,a2)
__device__ float g_sv[6][NN];          // s1_fwd, u_fwd, s1_bwd, u_bwd, s1_geo, u_geo
__device__ float g_s2[3][NN];          // s2 per adjacency
__device__ float g_m[3][NN];           // row max
__device__ float g_Z[3][NN];           // row softmax denom
__device__ int   g_cnt[3][NN];         // row neighbor counts
__device__ int   g_rowlist[3][NN * MAXD];
__device__ int   g_colcnt[NN];         // backward-adj column counts
__device__ int   g_collist[NN * MAXD]; // backward-adj column lists (CSC)
__device__ float g_gbuf[3][NN * FF];   // w_f@t, w_b^T@t, w_g@t

__device__ __forceinline__ float lrelu(float x) {
    return x > 0.f ? x : LRALPHA * x;
}

// ---- kernel 0: wa[k] = W @ a  (6 vectors of length F) ----
__global__ void proj_wa_kernel(const float* __restrict__ Wf, const float* __restrict__ af1, const float* __restrict__ af2,
                               const float* __restrict__ Wb, const float* __restrict__ ab1, const float* __restrict__ ab2,
                               const float* __restrict__ Wg, const float* __restrict__ ag1, const float* __restrict__ ag2) {
    int tid = threadIdx.x;            // 768 threads
    int k = tid >> 7;                 // 0..5
    int f = tid & 127;
    const float* W = (k < 2) ? Wf : (k < 4) ? Wb : Wg;
    const float* a = (k == 0) ? af1 : (k == 1) ? af2 : (k == 2) ? ab1 :
                     (k == 3) ? ab2 : (k == 4) ? ag1 : ag2;
    float acc = 0.f;
#pragma unroll
    for (int e = 0; e < EE; e++) acc += W[f * EE + e] * a[e];
    g_wa[k][f] = acc;
}

// ---- kernel 0b: sv[k][n] = t[n,:] . wa[k]  ----
__global__ void proj_sv_kernel(const float* __restrict__ t) {
    int n = blockIdx.x * blockDim.x + threadIdx.x;
    if (n >= NN) return;
    const float* tr = t + (size_t)n * FF;
    float acc[6] = {0.f, 0.f, 0.f, 0.f, 0.f, 0.f};
    for (int f = 0; f < FF; f++) {
        float tv = __ldg(tr + f);
#pragma unroll
        for (int k = 0; k < 6; k++) acc[k] += tv * g_wa[k][f];
    }
#pragma unroll
    for (int k = 0; k < 6; k++) g_sv[k][n] = acc[k];
}

// ---- zero the backward column counters (must be deterministic per call) ----
__global__ void zero_colcnt_kernel() {
    int i = blockIdx.x * blockDim.x + threadIdx.x;
    if (i < NN) g_colcnt[i] = 0;
}

// ---- kernel 1: scan each adjacency row once.
// Extract neighbor list, degree, and s2 = (adj . u) / deg. For backward adj also
// build the column (CSC) lists needed for w_b^T @ t. ----
__global__ void scan_kernel(const float* __restrict__ fwd,
                            const float* __restrict__ bwd,
                            const float* __restrict__ geo) {
    int a = blockIdx.y;               // 0=fwd, 1=bwd, 2=geo
    int row = blockIdx.x;
    const float* adj = (a == 0) ? fwd : (a == 1) ? bwd : geo;
    const float4* rp = reinterpret_cast<const float4*>(adj + (size_t)row * NN);

    __shared__ int scnt;
    __shared__ float sdot;
    if (threadIdx.x == 0) { scnt = 0; sdot = 0.f; }
    __syncthreads();

    const float* u = g_sv[2 * a + 1];
    int* list = &g_rowlist[a][(size_t)row * MAXD];
    float dot = 0.f;

    for (int i = threadIdx.x; i < NN / 4; i += blockDim.x) {
        float4 v = __ldg(rp + i);
        float vv[4] = {v.x, v.y, v.z, v.w};
#pragma unroll
        for (int q = 0; q < 4; q++) {
            if (vv[q] != 0.f) {
                int col = i * 4 + q;
                int p = atomicAdd(&scnt, 1);
                if (p < MAXD) list[p] = col;
                dot += u[col];
                if (a == 1) {
                    int pc = atomicAdd(&g_colcnt[col], 1);
                    if (pc < MAXD) g_collist[(size_t)col * MAXD + pc] = row;
                }
            }
        }
    }
    atomicAdd(&sdot, dot);
    __syncthreads();
    if (threadIdx.x == 0) {
        g_cnt[a][row] = min(scnt, MAXD);
        float deg = (scnt < 1) ? 1.f : (float)scnt;   // values are exactly 1.0 so deg == count
        g_s2[a][row] = sdot / deg;
    }
}

// ---- kernel 2: per-row softmax stats (max, denom). One warp per (adj,row). ----
__global__ void stats_kernel() {
    int gw = (blockIdx.x * blockDim.x + threadIdx.x) >> 5;
    int lane = threadIdx.x & 31;
    if (gw >= 3 * NN) return;
    int a = gw / NN;
    int row = gw % NN;
    int c = g_cnt[a][row];
    const int* list = &g_rowlist[a][(size_t)row * MAXD];
    float s1 = g_sv[2 * a][row];
    const float* s2 = g_s2[a];

    float mx = -3.0e38f;
    for (int j = lane; j < c; j += 32)
        mx = fmaxf(mx, lrelu(s1 + s2[list[j]]));
#pragma unroll
    for (int o = 16; o; o >>= 1) mx = fmaxf(mx, __shfl_xor_sync(0xffffffffu, mx, o));

    float z = 0.f;
    for (int j = lane; j < c; j += 32)
        z += __expf(lrelu(s1 + s2[list[j]]) - mx);
#pragma unroll
    for (int o = 16; o; o >>= 1) z += __shfl_xor_sync(0xffffffffu, z, o);

    if (lane == 0) { g_m[a][row] = mx; g_Z[a][row] = z; }
}

// ---- kernel 3: sparse aggregation.
//   a=0 (fwd):  g[i,:] = sum_j coef(i,j) t[j,:]   coef from row i's softmax
//   a=2 (geo):  same with geo lists
//   a=1 (bwd):  g[i,:] = sum_j w_b[j,i] t[j,:]    via column lists, per-j stats ----
__global__ void agg_kernel(const float* __restrict__ t) {
    int a = blockIdx.y;
    int row = blockIdx.x;
    __shared__ float scoef[MAXD];
    __shared__ int scol[MAXD];

    int c;
    const int* list;
    if (a == 1) {
        c = min(g_colcnt[row], MAXD);
        list = &g_collist[(size_t)row * MAXD];
    } else {
        c = g_cnt[a][row];
        list = &g_rowlist[a][(size_t)row * MAXD];
    }

    for (int j = threadIdx.x; j < c; j += blockDim.x) {
        int col = list[j];
        float coef;
        if (a == 1) {
            float x = lrelu(g_sv[2][col] + g_s2[1][row]);
            coef = __expf(x - g_m[1][col]) / g_Z[1][col];
        } else {
            float x = lrelu(g_sv[2 * a][row] + g_s2[a][col]);
            coef = __expf(x - g_m[a][row]) / g_Z[a][row];
        }
        scoef[j] = coef;
        scol[j] = col;
    }
    __syncthreads();

    int f = threadIdx.x;  // blockDim.x == FF
    float acc = 0.f;
    for (int j = 0; j < c; j++)
        acc += scoef[j] * __ldg(t + (size_t)scol[j] * FF + f);
    g_gbuf[a][(size_t)row * FF + f] = acc;
}

// ---- kernel 4: out[(c*64+e), n] = sum_f weight[e,f] * G_c[n,f]
//   G_0=t, G_1=g_fwd, G_2=g_bwd, G_3=g_geo.  Tile 64e x 32n per block. ----
__global__ void final_kernel(const float* __restrict__ t,
                             const float* __restrict__ weight,
                             float* __restrict__ out) {
    int cpart = blockIdx.y;           // 0..3
    int n0 = blockIdx.x * 32;
    const float* G = (cpart == 0) ? t : g_gbuf[cpart - 1];

    __shared__ float Gs[FF][32];      // 16 KB, [f][n] layout -> conflict-free reads
    __shared__ float Ws[EE][FF];      // 32 KB

    int tid = threadIdx.y * 32 + threadIdx.x;   // 256 threads
    for (int i = tid; i < 32 * FF; i += 256) {
        int nn = i & 31;
        int f = i >> 5;
        Gs[f][nn] = G[(size_t)(n0 + nn) * FF + f];
    }
    for (int i = tid; i < EE * FF; i += 256)
        Ws[i / FF][i % FF] = weight[i];
    __syncthreads();

    int tx = threadIdx.x;             // n within tile
    int ty = threadIdx.y;             // e group (8 e's each)
    float acc[8] = {0.f, 0.f, 0.f, 0.f, 0.f, 0.f, 0.f, 0.f};
    for (int f = 0; f < FF; f++) {
        float gv = Gs[f][tx];
#pragma unroll
        for (int eg = 0; eg < 8; eg++)
            acc[eg] += Ws[ty * 8 + eg][f] * gv;
    }
#pragma unroll
    for (int eg = 0; eg < 8; eg++) {
        int e = ty * 8 + eg;
        out[(size_t)(cpart * EE + e) * NN + n0 + tx] = acc[eg];
    }
}

extern "C" void kernel_launch(void* const* d_in, const int* in_sizes, int n_in,
                              void* d_out, int out_size) {
    const float* feat   = (const float*)d_in[0];
    const float* geo    = (const float*)d_in[1];
    const float* fwd    = (const float*)d_in[2];
    const float* bwd    = (const float*)d_in[3];
    const float* weight = (const float*)d_in[4];
    const float* Wf  = (const float*)d_in[5];
    const float* af1 = (const float*)d_in[6];
    const float* af2 = (const float*)d_in[7];
    const float* Wb  = (const float*)d_in[8];
    const float* ab1 = (const float*)d_in[9];
    const float* ab2 = (const float*)d_in[10];
    const float* Wg  = (const float*)d_in[11];
    const float* ag1 = (const float*)d_in[12];
    const float* ag2 = (const float*)d_in[13];
    float* out = (float*)d_out;

    zero_colcnt_kernel<<<NN / 256, 256>>>();
    proj_wa_kernel<<<1, 768>>>(Wf, af1, af2, Wb, ab1, ab2, Wg, ag1, ag2);
    proj_sv_kernel<<<NN / 256, 256>>>(feat);
    scan_kernel<<<dim3(NN, 3), 256>>>(fwd, bwd, geo);
    stats_kernel<<<(3 * NN) / 8, 256>>>();            // 8 warps/block
    agg_kernel<<<dim3(NN, 3), FF>>>(feat);
    final_kernel<<<dim3(NN / 32, 4), dim3(32, 8)>>>(feat, weight, out);
}

// round 2
// speedup vs baseline: 1.2450x; 1.2450x over previous
#include <cuda_runtime.h>

#define NN 4096
#define FF 128
#define EE 64
#define MAXD 192
#define LRALPHA 0.2f

// ---- scratch (device globals; no allocation allowed) ----
__device__ float g_wa[6][FF];          // W@a projected vectors
__device__ float g_sv[6][NN];          // s1_fwd, u_fwd, s1_bwd, u_bwd, s1_geo, u_geo
__device__ float g_s2[3][NN];          // s2 per adjacency
__device__ float g_m[3][NN];           // row max
__device__ float g_Z[3][NN];           // row softmax denom
__device__ int   g_cnt[3][NN];         // row neighbor counts
__device__ int   g_rowlist[3][NN * MAXD];
__device__ int   g_colcnt[NN];         // backward-adj column counts
__device__ int   g_collist[NN * MAXD]; // backward-adj column lists (CSC)
__device__ float g_gbuf[3][NN * FF];   // w_f@t, w_b^T@t, w_g@t

__device__ __forceinline__ float lrelu(float x) {
    return x > 0.f ? x : LRALPHA * x;
}

// ---- kernel 0 (fused): zero colcnt + wa[k] = W @ a ----
__global__ void init_kernel(const float* __restrict__ Wf, const float* __restrict__ af1, const float* __restrict__ af2,
                            const float* __restrict__ Wb, const float* __restrict__ ab1, const float* __restrict__ ab2,
                            const float* __restrict__ Wg, const float* __restrict__ ag1, const float* __restrict__ ag2) {
    if (blockIdx.x < 6) {
        int gt = blockIdx.x * 768 + threadIdx.x;
        if (gt < NN) g_colcnt[gt] = 0;
        return;
    }
    int tid = threadIdx.x;            // 768 threads
    int k = tid >> 7;                 // 0..5
    int f = tid & 127;
    const float* W = (k < 2) ? Wf : (k < 4) ? Wb : Wg;
    const float* a = (k == 0) ? af1 : (k == 1) ? af2 : (k == 2) ? ab1 :
                     (k == 3) ? ab2 : (k == 4) ? ag1 : ag2;
    float acc = 0.f;
#pragma unroll
    for (int e = 0; e < EE; e++) acc += W[f * EE + e] * a[e];
    g_wa[k][f] = acc;
}

// ---- kernel 0b: sv[k][n] = t[n,:] . wa[k] ----
__global__ void proj_sv_kernel(const float* __restrict__ t) {
    int n = blockIdx.x * blockDim.x + threadIdx.x;
    if (n >= NN) return;
    const float* tr = t + (size_t)n * FF;
    float acc[6] = {0.f, 0.f, 0.f, 0.f, 0.f, 0.f};
    for (int f = 0; f < FF; f++) {
        float tv = __ldg(tr + f);
#pragma unroll
        for (int k = 0; k < 6; k++) acc[k] += tv * g_wa[k][f];
    }
#pragma unroll
    for (int k = 0; k < 6; k++) g_sv[k][n] = acc[k];
}

// ---- kernel 1: scan each adjacency row once.
// All 4 uint4 loads batched up front; single OR-reduced branch region per 16
// elements (taken ~15%); rare path does list build + dot; warp-reduced sdot. ----
__global__ void scan_kernel(const float* __restrict__ fwd,
                            const float* __restrict__ bwd,
                            const float* __restrict__ geo) {
    int a = blockIdx.y;               // 0=fwd, 1=bwd, 2=geo
    int row = blockIdx.x;
    const float* adj = (a == 0) ? fwd : (a == 1) ? bwd : geo;
    const uint4* rp = reinterpret_cast<const uint4*>(adj + (size_t)row * NN);

    __shared__ int scnt;
    __shared__ float sdot;
    if (threadIdx.x == 0) { scnt = 0; sdot = 0.f; }
    __syncthreads();

    const float* u = g_sv[2 * a + 1];
    int* list = &g_rowlist[a][(size_t)row * MAXD];
    int t = threadIdx.x;
    float dot = 0.f;

    // batched loads: 16 elements per thread, coalesced, MLP=4
    uint4 v0 = __ldg(rp + t);
    uint4 v1 = __ldg(rp + t + 256);
    uint4 v2 = __ldg(rp + t + 512);
    uint4 v3 = __ldg(rp + t + 768);

    unsigned g0 = v0.x | v0.y | v0.z | v0.w;
    unsigned g1 = v1.x | v1.y | v1.z | v1.w;
    unsigned g2 = v2.x | v2.y | v2.z | v2.w;
    unsigned g3 = v3.x | v3.y | v3.z | v3.w;

    if ((g0 | g1 | g2 | g3) != 0u) {
        uint4 vs[4] = {v0, v1, v2, v3};
        unsigned gs[4] = {g0, g1, g2, g3};
#pragma unroll
        for (int k = 0; k < 4; k++) {
            if (gs[k] != 0u) {
                int base = (t + k * 256) * 4;
                unsigned vv[4] = {vs[k].x, vs[k].y, vs[k].z, vs[k].w};
#pragma unroll
                for (int q = 0; q < 4; q++) {
                    if (vv[q] != 0u) {
                        int col = base + q;
                        int p = atomicAdd(&scnt, 1);
                        if (p < MAXD) list[p] = col;
                        dot += u[col];
                        if (a == 1) {
                            int pc = atomicAdd(&g_colcnt[col], 1);
                            if (pc < MAXD) g_collist[(size_t)col * MAXD + pc] = row;
                        }
                    }
                }
            }
        }
    }

    // warp-reduce dot, one shared atomic per warp
#pragma unroll
    for (int o = 16; o; o >>= 1) dot += __shfl_xor_sync(0xffffffffu, dot, o);
    if ((t & 31) == 0) atomicAdd(&sdot, dot);
    __syncthreads();

    if (threadIdx.x == 0) {
        int c = scnt;
        g_cnt[a][row] = min(c, MAXD);
        float deg = (c < 1) ? 1.f : (float)c;
        g_s2[a][row] = sdot / deg;
    }
}

// ---- kernel 2: per-row softmax stats. One warp per (adj,row).
// Single gather pass: values cached in registers (MAXD/32 = 6 per lane). ----
__global__ void stats_kernel() {
    int gw = (blockIdx.x * blockDim.x + threadIdx.x) >> 5;
    int lane = threadIdx.x & 31;
    if (gw >= 3 * NN) return;
    int a = gw / NN;
    int row = gw % NN;
    int c = g_cnt[a][row];
    const int* list = &g_rowlist[a][(size_t)row * MAXD];
    float s1 = g_sv[2 * a][row];
    const float* s2 = g_s2[a];

    float vals[MAXD / 32];
    float mx = -3.0e38f;
#pragma unroll
    for (int k = 0; k < MAXD / 32; k++) {
        int j = lane + k * 32;
        float v = (j < c) ? lrelu(s1 + s2[list[j]]) : -3.0e38f;
        vals[k] = v;
        mx = fmaxf(mx, v);
    }
#pragma unroll
    for (int o = 16; o; o >>= 1) mx = fmaxf(mx, __shfl_xor_sync(0xffffffffu, mx, o));

    float z = 0.f;
#pragma unroll
    for (int k = 0; k < MAXD / 32; k++) {
        int j = lane + k * 32;
        if (j < c) z += __expf(vals[k] - mx);
    }
#pragma unroll
    for (int o = 16; o; o >>= 1) z += __shfl_xor_sync(0xffffffffu, z, o);

    if (lane == 0) { g_m[a][row] = mx; g_Z[a][row] = z; }
}

// ---- kernel 3: sparse aggregation (unroll-4 gather with 4 acc chains). ----
__global__ void agg_kernel(const float* __restrict__ t) {
    int a = blockIdx.y;
    int row = blockIdx.x;
    __shared__ float scoef[MAXD];
    __shared__ int scol[MAXD];

    int c;
    const int* list;
    if (a == 1) {
        c = min(g_colcnt[row], MAXD);
        list = &g_collist[(size_t)row * MAXD];
    } else {
        c = g_cnt[a][row];
        list = &g_rowlist[a][(size_t)row * MAXD];
    }

    for (int j = threadIdx.x; j < c; j += blockDim.x) {
        int col = list[j];
        float coef;
        if (a == 1) {
            float x = lrelu(g_sv[2][col] + g_s2[1][row]);
            coef = __expf(x - g_m[1][col]) / g_Z[1][col];
        } else {
            float x = lrelu(g_sv[2 * a][row] + g_s2[a][col]);
            coef = __expf(x - g_m[a][row]) / g_Z[a][row];
        }
        scoef[j] = coef;
        scol[j] = col;
    }
    __syncthreads();

    int f = threadIdx.x;  // blockDim.x == FF
    float a0 = 0.f, a1 = 0.f, a2 = 0.f, a3 = 0.f;
    int j = 0;
    for (; j + 4 <= c; j += 4) {
        a0 += scoef[j + 0] * __ldg(t + (size_t)scol[j + 0] * FF + f);
        a1 += scoef[j + 1] * __ldg(t + (size_t)scol[j + 1] * FF + f);
        a2 += scoef[j + 2] * __ldg(t + (size_t)scol[j + 2] * FF + f);
        a3 += scoef[j + 3] * __ldg(t + (size_t)scol[j + 3] * FF + f);
    }
    for (; j < c; j++)
        a0 += scoef[j] * __ldg(t + (size_t)scol[j] * FF + f);
    g_gbuf[a][(size_t)row * FF + f] = (a0 + a1) + (a2 + a3);
}

// ---- kernel 4: out[(c*64+e), n] = sum_f weight[e,f] * G_c[n,f] ----
__global__ void final_kernel(const float* __restrict__ t,
                             const float* __restrict__ weight,
                             float* __restrict__ out) {
    int cpart = blockIdx.y;           // 0..3
    int n0 = blockIdx.x * 32;
    const float* G = (cpart == 0) ? t : g_gbuf[cpart - 1];

    __shared__ float Gs[FF][32];
    __shared__ float Ws[EE][FF];

    int tid = threadIdx.y * 32 + threadIdx.x;   // 256 threads
    for (int i = tid; i < 32 * FF; i += 256) {
        int nn = i & 31;
        int f = i >> 5;
        Gs[f][nn] = G[(size_t)(n0 + nn) * FF + f];
    }
    for (int i = tid; i < EE * FF; i += 256)
        Ws[i / FF][i % FF] = weight[i];
    __syncthreads();

    int tx = threadIdx.x;
    int ty = threadIdx.y;
    float acc[8] = {0.f, 0.f, 0.f, 0.f, 0.f, 0.f, 0.f, 0.f};
    for (int f = 0; f < FF; f++) {
        float gv = Gs[f][tx];
#pragma unroll
        for (int eg = 0; eg < 8; eg++)
            acc[eg] += Ws[ty * 8 + eg][f] * gv;
    }
#pragma unroll
    for (int eg = 0; eg < 8; eg++) {
        int e = ty * 8 + eg;
        out[(size_t)(cpart * EE + e) * NN + n0 + tx] = acc[eg];
    }
}

extern "C" void kernel_launch(void* const* d_in, const int* in_sizes, int n_in,
                              void* d_out, int out_size) {
    const float* feat   = (const float*)d_in[0];
    const float* geo    = (const float*)d_in[1];
    const float* fwd    = (const float*)d_in[2];
    const float* bwd    = (const float*)d_in[3];
    const float* weight = (const float*)d_in[4];
    const float* Wf  = (const float*)d_in[5];
    const float* af1 = (const float*)d_in[6];
    const float* af2 = (const float*)d_in[7];
    const float* Wb  = (const float*)d_in[8];
    const float* ab1 = (const float*)d_in[9];
    const float* ab2 = (const float*)d_in[10];
    const float* Wg  = (const float*)d_in[11];
    const float* ag1 = (const float*)d_in[12];
    const float* ag2 = (const float*)d_in[13];
    float* out = (float*)d_out;

    init_kernel<<<7, 768>>>(Wf, af1, af2, Wb, ab1, ab2, Wg, ag1, ag2);
    proj_sv_kernel<<<NN / 256, 256>>>(feat);
    scan_kernel<<<dim3(NN, 3), 256>>>(fwd, bwd, geo);
    stats_kernel<<<(3 * NN) / 8, 256>>>();
    agg_kernel<<<dim3(NN, 3), FF>>>(feat);
    final_kernel<<<dim3(NN / 32, 4), dim3(32, 8)>>>(feat, weight, out);
}

// round 3
// speedup vs baseline: 1.5558x; 1.2496x over previous
#include <cuda_runtime.h>

#define NN 4096
#define FF 128
#define EE 64
#define MAXD 192
#define LRALPHA 0.2f
#define FULLW 0xffffffffu

// ---- scratch (device globals) ----
__device__ float g_wa[6][FF];
__device__ float g_sv[6][NN];          // s1_fwd, u_fwd, s1_bwd, u_bwd, s1_geo, u_geo
__device__ float g_s2[3][NN];
__device__ float g_m[NN];              // bwd row max
__device__ float g_Z[NN];              // bwd row denom
__device__ int   g_cnt[3][NN];
__device__ int   g_rowlist[3][NN * MAXD];
__device__ int   g_colcnt[NN];
__device__ int   g_collist[NN * MAXD];
__device__ float g_gbuf[3][NN * FF];

__device__ __forceinline__ float lrelu(float x) {
    return x > 0.f ? x : LRALPHA * x;
}

// ---- kernel 0 (fused): zero colcnt + wa[k] = W @ a ----
__global__ void init_kernel(const float* __restrict__ Wf, const float* __restrict__ af1, const float* __restrict__ af2,
                            const float* __restrict__ Wb, const float* __restrict__ ab1, const float* __restrict__ ab2,
                            const float* __restrict__ Wg, const float* __restrict__ ag1, const float* __restrict__ ag2) {
    if (blockIdx.x < 6) {
        int gt = blockIdx.x * 768 + threadIdx.x;
        if (gt < NN) g_colcnt[gt] = 0;
        return;
    }
    int tid = threadIdx.x;            // 768 threads
    int k = tid >> 7;
    int f = tid & 127;
    const float* W = (k < 2) ? Wf : (k < 4) ? Wb : Wg;
    const float* a = (k == 0) ? af1 : (k == 1) ? af2 : (k == 2) ? ab1 :
                     (k == 3) ? ab2 : (k == 4) ? ag1 : ag2;
    float acc = 0.f;
#pragma unroll
    for (int e = 0; e < EE; e++) acc += W[f * EE + e] * a[e];
    g_wa[k][f] = acc;
}

// ---- kernel 0b: sv[k][n] = t[n,:] . wa[k]; warp per row, float4 coalesced ----
__global__ void proj_sv_kernel(const float* __restrict__ t) {
    __shared__ float swa[6][FF];
    int tid = threadIdx.x;            // 256
    for (int i = tid; i < 6 * FF; i += 256)
        ((float*)swa)[i] = ((const float*)g_wa)[i];
    __syncthreads();
    int wid = tid >> 5, lane = tid & 31;
    int row = blockIdx.x * 8 + wid;
    const float4* t4 = reinterpret_cast<const float4*>(t + (size_t)row * FF);
    float4 v = __ldg(t4 + lane);
    float acc[6];
#pragma unroll
    for (int k = 0; k < 6; k++) {
        float4 w = reinterpret_cast<const float4*>(swa[k])[lane];
        acc[k] = v.x * w.x + v.y * w.y + v.z * w.z + v.w * w.w;
    }
#pragma unroll
    for (int k = 0; k < 6; k++) {
        float s = acc[k];
#pragma unroll
        for (int o = 16; o; o >>= 1) s += __shfl_xor_sync(FULLW, s, o);
        if (lane == 0) g_sv[k][row] = s;
    }
}

// ---- kernel 1: adjacency scan, warp-compaction (no per-element atomics) ----
__global__ void scan_kernel(const float* __restrict__ fwd,
                            const float* __restrict__ bwd,
                            const float* __restrict__ geo) {
    int a = blockIdx.y;
    int row = blockIdx.x;
    const float* adj = (a == 0) ? fwd : (a == 1) ? bwd : geo;
    const uint4* rp = reinterpret_cast<const uint4*>(adj + (size_t)row * NN);

    __shared__ int scnt;
    __shared__ float sdot;
    if (threadIdx.x == 0) { scnt = 0; sdot = 0.f; }
    __syncthreads();

    const float* u = g_sv[2 * a + 1];
    int* list = &g_rowlist[a][(size_t)row * MAXD];
    int t = threadIdx.x;
    int lane = t & 31;

    // 16 elements per thread, 4 loads in flight
    uint4 v0 = __ldg(rp + t);
    uint4 v1 = __ldg(rp + t + 256);
    uint4 v2 = __ldg(rp + t + 512);
    uint4 v3 = __ldg(rp + t + 768);

    // per-thread nonzero bitmask (branch-free)
    unsigned mask = 0;
    mask |= (v0.x != 0u) << 0;  mask |= (v0.y != 0u) << 1;
    mask |= (v0.z != 0u) << 2;  mask |= (v0.w != 0u) << 3;
    mask |= (v1.x != 0u) << 4;  mask |= (v1.y != 0u) << 5;
    mask |= (v1.z != 0u) << 6;  mask |= (v1.w != 0u) << 7;
    mask |= (v2.x != 0u) << 8;  mask |= (v2.y != 0u) << 9;
    mask |= (v2.z != 0u) << 10; mask |= (v2.w != 0u) << 11;
    mask |= (v3.x != 0u) << 12; mask |= (v3.y != 0u) << 13;
    mask |= (v3.z != 0u) << 14; mask |= (v3.w != 0u) << 15;

    int cnt = __popc(mask);
    // warp inclusive scan of cnt
    int incl = cnt;
#pragma unroll
    for (int d = 1; d < 32; d <<= 1) {
        int nb = __shfl_up_sync(FULLW, incl, d);
        if (lane >= d) incl += nb;
    }
    int warpTotal = __shfl_sync(FULLW, incl, 31);
    int excl = incl - cnt;
    int wb = 0;
    if (lane == 0 && warpTotal) wb = atomicAdd(&scnt, warpTotal);
    wb = __shfl_sync(FULLW, wb, 0);
    int base = wb + excl;

    float dot = 0.f;
    unsigned m = mask;
    while (m) {
        int b = __ffs(m) - 1;
        m &= m - 1;
        int col = (t << 2) + ((b >> 2) << 10) + (b & 3);
        if (base < MAXD) list[base] = col;
        base++;
        dot += u[col];
        if (a == 1) {
            int pc = atomicAdd(&g_colcnt[col], 1);
            if (pc < MAXD) g_collist[(size_t)col * MAXD + pc] = row;
        }
    }

#pragma unroll
    for (int o = 16; o; o >>= 1) dot += __shfl_xor_sync(FULLW, dot, o);
    if (lane == 0) atomicAdd(&sdot, dot);
    __syncthreads();

    if (threadIdx.x == 0) {
        int c = scnt;
        g_cnt[a][row] = min(c, MAXD);
        float deg = (c < 1) ? 1.f : (float)c;
        g_s2[a][row] = sdot / deg;
    }
}

// ---- kernel 2: softmax stats for BACKWARD rows only (needed cross-row by agg) ----
__global__ void stats_bwd_kernel() {
    int gw = (blockIdx.x * blockDim.x + threadIdx.x) >> 5;
    int lane = threadIdx.x & 31;
    if (gw >= NN) return;
    int row = gw;
    int c = g_cnt[1][row];
    const int* list = &g_rowlist[1][(size_t)row * MAXD];
    float s1 = g_sv[2][row];
    const float* s2 = g_s2[1];

    float vals[MAXD / 32];
    float mx = -3.0e38f;
#pragma unroll
    for (int k = 0; k < MAXD / 32; k++) {
        int j = lane + k * 32;
        float v = (j < c) ? lrelu(s1 + s2[list[j]]) : -3.0e38f;
        vals[k] = v;
        mx = fmaxf(mx, v);
    }
#pragma unroll
    for (int o = 16; o; o >>= 1) mx = fmaxf(mx, __shfl_xor_sync(FULLW, mx, o));

    float z = 0.f;
#pragma unroll
    for (int k = 0; k < MAXD / 32; k++) {
        int j = lane + k * 32;
        if (j < c) z += __expf(vals[k] - mx);
    }
#pragma unroll
    for (int o = 16; o; o >>= 1) z += __shfl_xor_sync(FULLW, z, o);

    if (lane == 0) { g_m[row] = mx; g_Z[row] = z; }
}

// ---- kernel 3: sparse aggregation. Fused row-softmax for fwd/geo;
// float4 quad gather (4 edges in flight, LDG.128). ----
__global__ void agg_kernel(const float* __restrict__ t) {
    int a = blockIdx.y;
    int row = blockIdx.x;
    __shared__ int scol[MAXD];
    __shared__ float scoef[MAXD];
    __shared__ float red[4];
    __shared__ float part[4][FF];

    int tid = threadIdx.x;            // 128
    int lane = tid & 31, wid = tid >> 5;

    int c;
    const int* list;
    if (a == 1) {
        c = min(g_colcnt[row], MAXD);
        list = &g_collist[(size_t)row * MAXD];
    } else {
        c = g_cnt[a][row];
        list = &g_rowlist[a][(size_t)row * MAXD];
    }

    if (a == 1) {
        float s2r = g_s2[1][row];
        for (int j = tid; j < c; j += 128) {
            int col = list[j];
            scol[j] = col;
            float x = lrelu(g_sv[2][col] + s2r);
            scoef[j] = __expf(x - g_m[col]) / g_Z[col];
        }
    } else {
        float s1 = g_sv[2 * a][row];
        const float* s2 = g_s2[a];
        float lm = -3.0e38f;
        for (int j = tid; j < c; j += 128) {
            int col = list[j];
            scol[j] = col;
            float x = lrelu(s1 + s2[col]);
            scoef[j] = x;
            lm = fmaxf(lm, x);
        }
#pragma unroll
        for (int o = 16; o; o >>= 1) lm = fmaxf(lm, __shfl_xor_sync(FULLW, lm, o));
        if (lane == 0) red[wid] = lm;
        __syncthreads();
        float mx = fmaxf(fmaxf(red[0], red[1]), fmaxf(red[2], red[3]));
        __syncthreads();                 // protect red before reuse
        float lz = 0.f;
        for (int j = tid; j < c; j += 128) {
            float e = __expf(scoef[j] - mx);
            scoef[j] = e;
            lz += e;
        }
#pragma unroll
        for (int o = 16; o; o >>= 1) lz += __shfl_xor_sync(FULLW, lz, o);
        if (lane == 0) red[wid] = lz;
        __syncthreads();
        float inv = 1.f / (red[0] + red[1] + red[2] + red[3]);
        for (int j = tid; j < c; j += 128) scoef[j] *= inv;
    }
    __syncthreads();

    // gather: quad q handles edges j = q, q+4, q+8, ... ; each lane loads float4
    const float4* t4 = reinterpret_cast<const float4*>(t);
    int quad = tid >> 5;
    float4 acc0 = {0.f, 0.f, 0.f, 0.f};
    float4 acc1 = {0.f, 0.f, 0.f, 0.f};
    int j = quad;
    for (; j + 4 < c; j += 8) {
        float cf0 = scoef[j];
        float cf1 = scoef[j + 4];
        float4 va = __ldg(t4 + (size_t)scol[j] * 32 + lane);
        float4 vb = __ldg(t4 + (size_t)scol[j + 4] * 32 + lane);
        acc0.x += cf0 * va.x; acc0.y += cf0 * va.y; acc0.z += cf0 * va.z; acc0.w += cf0 * va.w;
        acc1.x += cf1 * vb.x; acc1.y += cf1 * vb.y; acc1.z += cf1 * vb.z; acc1.w += cf1 * vb.w;
    }
    if (j < c) {
        float cf = scoef[j];
        float4 v = __ldg(t4 + (size_t)scol[j] * 32 + lane);
        acc0.x += cf * v.x; acc0.y += cf * v.y; acc0.z += cf * v.z; acc0.w += cf * v.w;
    }
    acc0.x += acc1.x; acc0.y += acc1.y; acc0.z += acc1.z; acc0.w += acc1.w;
    reinterpret_cast<float4*>(part[quad])[lane] = acc0;
    __syncthreads();

    int f = tid;   // 0..127
    float s = part[0][f] + part[1][f] + part[2][f] + part[3][f];
    g_gbuf[a][(size_t)row * FF + f] = s;
}

// ---- kernel 4: out[(c*64+e), n] = sum_f weight[e,f] * G_c[n,f] ----
__global__ void final_kernel(const float* __restrict__ t,
                             const float* __restrict__ weight,
                             float* __restrict__ out) {
    int cpart = blockIdx.y;
    int n0 = blockIdx.x * 32;
    const float* G = (cpart == 0) ? t : g_gbuf[cpart - 1];

    __shared__ float Gs[FF][32];
    __shared__ float Ws[EE][FF];

    int tid = threadIdx.y * 32 + threadIdx.x;   // 256
    for (int i = tid; i < 32 * FF; i += 256) {
        int nn = i & 31;
        int f = i >> 5;
        Gs[f][nn] = G[(size_t)(n0 + nn) * FF + f];
    }
    for (int i = tid; i < EE * FF; i += 256)
        Ws[i / FF][i % FF] = weight[i];
    __syncthreads();

    int tx = threadIdx.x;
    int ty = threadIdx.y;
    float acc[8] = {0.f, 0.f, 0.f, 0.f, 0.f, 0.f, 0.f, 0.f};
    for (int f = 0; f < FF; f++) {
        float gv = Gs[f][tx];
#pragma unroll
        for (int eg = 0; eg < 8; eg++)
            acc[eg] += Ws[ty * 8 + eg][f] * gv;
    }
#pragma unroll
    for (int eg = 0; eg < 8; eg++) {
        int e = ty * 8 + eg;
        out[(size_t)(cpart * EE + e) * NN + n0 + tx] = acc[eg];
    }
}

extern "C" void kernel_launch(void* const* d_in, const int* in_sizes, int n_in,
                              void* d_out, int out_size) {
    const float* feat   = (const float*)d_in[0];
    const float* geo    = (const float*)d_in[1];
    const float* fwd    = (const float*)d_in[2];
    const float* bwd    = (const float*)d_in[3];
    const float* weight = (const float*)d_in[4];
    const float* Wf  = (const float*)d_in[5];
    const float* af1 = (const float*)d_in[6];
    const float* af2 = (const float*)d_in[7];
    const float* Wb  = (const float*)d_in[8];
    const float* ab1 = (const float*)d_in[9];
    const float* ab2 = (const float*)d_in[10];
    const float* Wg  = (const float*)d_in[11];
    const float* ag1 = (const float*)d_in[12];
    const float* ag2 = (const float*)d_in[13];
    float* out = (float*)d_out;

    init_kernel<<<7, 768>>>(Wf, af1, af2, Wb, ab1, ab2, Wg, ag1, ag2);
    proj_sv_kernel<<<NN / 8, 256>>>(feat);
    scan_kernel<<<dim3(NN, 3), 256>>>(fwd, bwd, geo);
    stats_bwd_kernel<<<NN / 8, 256>>>();
    agg_kernel<<<dim3(NN, 3), 128>>>(feat);
    final_kernel<<<dim3(NN / 32, 4), dim3(32, 8)>>>(feat, weight, out);
}

// round 4
// speedup vs baseline: 1.8306x; 1.1766x over previous
#include <cuda_runtime.h>

#define NN 4096
#define FF 128
#define EE 64
#define MAXD 192
#define LRALPHA 0.2f
#define FULLW 0xffffffffu

// ---- scratch (device globals) ----
__device__ float g_wa[6][FF];
__device__ float g_sv[6][NN];          // s1_fwd, u_fwd, s1_bwd, u_bwd, s1_geo, u_geo
__device__ float g_s2[3][NN];
__device__ float g_m[NN];              // bwd row max
__device__ float g_Z[NN];              // bwd row denom
__device__ int   g_cnt[3][NN];
__device__ int   g_rowlist[3][NN * MAXD];
__device__ int   g_colcnt[NN];
__device__ int   g_collist[NN * MAXD];
__device__ float g_yt[NN * EE];        // yt[n][e] = (weight @ t^T)[e][n]

__device__ __forceinline__ float lrelu(float x) {
    return x > 0.f ? x : LRALPHA * x;
}

// ---- kernel 0 (fused): zero colcnt + wa[k] = W @ a ----
__global__ void init_kernel(const float* __restrict__ Wf, const float* __restrict__ af1, const float* __restrict__ af2,
                            const float* __restrict__ Wb, const float* __restrict__ ab1, const float* __restrict__ ab2,
                            const float* __restrict__ Wg, const float* __restrict__ ag1, const float* __restrict__ ag2) {
    if (blockIdx.x < 6) {
        int gt = blockIdx.x * 768 + threadIdx.x;
        if (gt < NN) g_colcnt[gt] = 0;
        return;
    }
    int tid = threadIdx.x;            // 768 threads
    int k = tid >> 7;
    int f = tid & 127;
    const float* W = (k < 2) ? Wf : (k < 4) ? Wb : Wg;
    const float* a = (k == 0) ? af1 : (k == 1) ? af2 : (k == 2) ? ab1 :
                     (k == 3) ? ab2 : (k == 4) ? ag1 : ag2;
    float acc = 0.f;
#pragma unroll
    for (int e = 0; e < EE; e++) acc += W[f * EE + e] * a[e];
    g_wa[k][f] = acc;
}

// ---- kernel 0b: sv[k][n] = t[n,:] . wa[k]; warp per row ----
__global__ void proj_sv_kernel(const float* __restrict__ t) {
    __shared__ float swa[6][FF];
    int tid = threadIdx.x;            // 256
    for (int i = tid; i < 6 * FF; i += 256)
        ((float*)swa)[i] = ((const float*)g_wa)[i];
    __syncthreads();
    int wid = tid >> 5, lane = tid & 31;
    int row = blockIdx.x * 8 + wid;
    const float4* t4 = reinterpret_cast<const float4*>(t + (size_t)row * FF);
    float4 v = __ldg(t4 + lane);
    float acc[6];
#pragma unroll
    for (int k = 0; k < 6; k++) {
        float4 w = reinterpret_cast<const float4*>(swa[k])[lane];
        acc[k] = v.x * w.x + v.y * w.y + v.z * w.z + v.w * w.w;
    }
#pragma unroll
    for (int k = 0; k < 6; k++) {
        float s = acc[k];
#pragma unroll
        for (int o = 16; o; o >>= 1) s += __shfl_xor_sync(FULLW, s, o);
        if (lane == 0) g_sv[k][row] = s;
    }
}

// ---- kernel 0c: y = weight @ t^T.  out part 0 directly + transposed copy g_yt ----
__global__ void y_kernel(const float* __restrict__ t,
                         const float* __restrict__ weight,
                         float* __restrict__ out) {
    int n0 = blockIdx.x * 32;
    __shared__ float Gs[FF][32];
    __shared__ float Ws[EE][FF];

    int tid = threadIdx.y * 32 + threadIdx.x;   // 256
    for (int i = tid; i < 32 * FF; i += 256) {
        int nn = i & 31;
        int f = i >> 5;
        Gs[f][nn] = t[(size_t)(n0 + nn) * FF + f];
    }
    for (int i = tid; i < EE * FF; i += 256)
        Ws[i / FF][i % FF] = weight[i];
    __syncthreads();

    int tx = threadIdx.x;
    int ty = threadIdx.y;
    float acc[8] = {0.f, 0.f, 0.f, 0.f, 0.f, 0.f, 0.f, 0.f};
    for (int f = 0; f < FF; f++) {
        float gv = Gs[f][tx];
#pragma unroll
        for (int eg = 0; eg < 8; eg++)
            acc[eg] += Ws[ty * 8 + eg][f] * gv;
    }
#pragma unroll
    for (int eg = 0; eg < 8; eg++) {
        int e = ty * 8 + eg;
        out[(size_t)e * NN + n0 + tx] = acc[eg];
        g_yt[(size_t)(n0 + tx) * EE + e] = acc[eg];
    }
}

// ---- kernel 1: adjacency scan, warp-compaction ----
__global__ void scan_kernel(const float* __restrict__ fwd,
                            const float* __restrict__ bwd,
                            const float* __restrict__ geo) {
    int a = blockIdx.y;
    int row = blockIdx.x;
    const float* adj = (a == 0) ? fwd : (a == 1) ? bwd : geo;
    const uint4* rp = reinterpret_cast<const uint4*>(adj + (size_t)row * NN);

    __shared__ int scnt;
    __shared__ float sdot;
    if (threadIdx.x == 0) { scnt = 0; sdot = 0.f; }
    __syncthreads();

    const float* u = g_sv[2 * a + 1];
    int* list = &g_rowlist[a][(size_t)row * MAXD];
    int t = threadIdx.x;
    int lane = t & 31;

    uint4 v0 = __ldg(rp + t);
    uint4 v1 = __ldg(rp + t + 256);
    uint4 v2 = __ldg(rp + t + 512);
    uint4 v3 = __ldg(rp + t + 768);

    unsigned mask = 0;
    mask |= (v0.x != 0u) << 0;  mask |= (v0.y != 0u) << 1;
    mask |= (v0.z != 0u) << 2;  mask |= (v0.w != 0u) << 3;
    mask |= (v1.x != 0u) << 4;  mask |= (v1.y != 0u) << 5;
    mask |= (v1.z != 0u) << 6;  mask |= (v1.w != 0u) << 7;
    mask |= (v2.x != 0u) << 8;  mask |= (v2.y != 0u) << 9;
    mask |= (v2.z != 0u) << 10; mask |= (v2.w != 0u) << 11;
    mask |= (v3.x != 0u) << 12; mask |= (v3.y != 0u) << 13;
    mask |= (v3.z != 0u) << 14; mask |= (v3.w != 0u) << 15;

    int cnt = __popc(mask);
    int incl = cnt;
#pragma unroll
    for (int d = 1; d < 32; d <<= 1) {
        int nb = __shfl_up_sync(FULLW, incl, d);
        if (lane >= d) incl += nb;
    }
    int warpTotal = __shfl_sync(FULLW, incl, 31);
    int excl = incl - cnt;
    int wb = 0;
    if (lane == 0 && warpTotal) wb = atomicAdd(&scnt, warpTotal);
    wb = __shfl_sync(FULLW, wb, 0);
    int base = wb + excl;

    float dot = 0.f;
    unsigned m = mask;
    while (m) {
        int b = __ffs(m) - 1;
        m &= m - 1;
        int col = (t << 2) + ((b >> 2) << 10) + (b & 3);
        if (base < MAXD) list[base] = col;
        base++;
        dot += u[col];
        if (a == 1) {
            int pc = atomicAdd(&g_colcnt[col], 1);
            if (pc < MAXD) g_collist[(size_t)col * MAXD + pc] = row;
        }
    }

#pragma unroll
    for (int o = 16; o; o >>= 1) dot += __shfl_xor_sync(FULLW, dot, o);
    if (lane == 0) atomicAdd(&sdot, dot);
    __syncthreads();

    if (threadIdx.x == 0) {
        int c = scnt;
        g_cnt[a][row] = min(c, MAXD);
        float deg = (c < 1) ? 1.f : (float)c;
        g_s2[a][row] = sdot / deg;
    }
}

// ---- kernel 2: softmax stats for BACKWARD rows ----
__global__ void stats_bwd_kernel() {
    int gw = (blockIdx.x * blockDim.x + threadIdx.x) >> 5;
    int lane = threadIdx.x & 31;
    if (gw >= NN) return;
    int row = gw;
    int c = g_cnt[1][row];
    const int* list = &g_rowlist[1][(size_t)row * MAXD];
    float s1 = g_sv[2][row];
    const float* s2 = g_s2[1];

    float vals[MAXD / 32];
    float mx = -3.0e38f;
#pragma unroll
    for (int k = 0; k < MAXD / 32; k++) {
        int j = lane + k * 32;
        float v = (j < c) ? lrelu(s1 + s2[list[j]]) : -3.0e38f;
        vals[k] = v;
        mx = fmaxf(mx, v);
    }
#pragma unroll
    for (int o = 16; o; o >>= 1) mx = fmaxf(mx, __shfl_xor_sync(FULLW, mx, o));

    float z = 0.f;
#pragma unroll
    for (int k = 0; k < MAXD / 32; k++) {
        int j = lane + k * 32;
        if (j < c) z += __expf(vals[k] - mx);
    }
#pragma unroll
    for (int o = 16; o; o >>= 1) z += __shfl_xor_sync(FULLW, z, o);

    if (lane == 0) { g_m[row] = mx; g_Z[row] = z; }
}

// ---- kernel 3: E-domain aggregation. Warp per row, 8 rows per block.
//   part (a+1): out[(a+1)*64+e, i] = sum_j coef(i,j) * yt[j][e]
//   fused row softmax for fwd/geo; CSC + precomputed stats for bwd. ----
__global__ void aggE_kernel(float* __restrict__ out) {
    int a = blockIdx.y;
    int base = blockIdx.x * 8;
    int tid = threadIdx.x;            // 256
    int wid = tid >> 5, lane = tid & 31;
    int row = base + wid;

    __shared__ float scoef[8][MAXD];
    __shared__ int   scol[8][MAXD];
    __shared__ float sres[8][EE];

    int c;
    const int* list;
    if (a == 1) {
        c = min(g_colcnt[row], MAXD);
        list = &g_collist[(size_t)row * MAXD];
    } else {
        c = g_cnt[a][row];
        list = &g_rowlist[a][(size_t)row * MAXD];
    }

    if (a == 1) {
        float s2r = g_s2[1][row];
#pragma unroll
        for (int k = 0; k < MAXD / 32; k++) {
            int j = lane + k * 32;
            if (j < c) {
                int col = list[j];
                float x = lrelu(g_sv[2][col] + s2r);
                scoef[wid][j] = __expf(x - g_m[col]) / g_Z[col];
                scol[wid][j] = col;
            }
        }
    } else {
        float s1 = g_sv[2 * a][row];
        const float* s2 = g_s2[a];
        float vals[MAXD / 32];
        int cols[MAXD / 32];
        float mx = -3.0e38f;
#pragma unroll
        for (int k = 0; k < MAXD / 32; k++) {
            int j = lane + k * 32;
            if (j < c) {
                int col = list[j];
                cols[k] = col;
                float x = lrelu(s1 + s2[col]);
                vals[k] = x;
                mx = fmaxf(mx, x);
            } else vals[k] = -3.0e38f;
        }
#pragma unroll
        for (int o = 16; o; o >>= 1) mx = fmaxf(mx, __shfl_xor_sync(FULLW, mx, o));
        float z = 0.f;
#pragma unroll
        for (int k = 0; k < MAXD / 32; k++) {
            int j = lane + k * 32;
            if (j < c) { float e = __expf(vals[k] - mx); vals[k] = e; z += e; }
        }
#pragma unroll
        for (int o = 16; o; o >>= 1) z += __shfl_xor_sync(FULLW, z, o);
        float inv = 1.f / z;
#pragma unroll
        for (int k = 0; k < MAXD / 32; k++) {
            int j = lane + k * 32;
            if (j < c) { scoef[wid][j] = vals[k] * inv; scol[wid][j] = cols[k]; }
        }
    }
    __syncwarp();

    // gather: lane handles e = 2*lane, 2*lane+1 (float2); 4 edges in flight
    const float2* y2 = reinterpret_cast<const float2*>(g_yt);
    float2 a0 = {0.f, 0.f}, a1 = {0.f, 0.f}, a2 = {0.f, 0.f}, a3 = {0.f, 0.f};
    int j = 0;
    for (; j + 4 <= c; j += 4) {
        float c0 = scoef[wid][j + 0]; int l0 = scol[wid][j + 0];
        float c1 = scoef[wid][j + 1]; int l1 = scol[wid][j + 1];
        float c2 = scoef[wid][j + 2]; int l2 = scol[wid][j + 2];
        float c3 = scoef[wid][j + 3]; int l3 = scol[wid][j + 3];
        float2 v0 = __ldg(y2 + (size_t)l0 * 32 + lane);
        float2 v1 = __ldg(y2 + (size_t)l1 * 32 + lane);
        float2 v2 = __ldg(y2 + (size_t)l2 * 32 + lane);
        float2 v3 = __ldg(y2 + (size_t)l3 * 32 + lane);
        a0.x += c0 * v0.x; a0.y += c0 * v0.y;
        a1.x += c1 * v1.x; a1.y += c1 * v1.y;
        a2.x += c2 * v2.x; a2.y += c2 * v2.y;
        a3.x += c3 * v3.x; a3.y += c3 * v3.y;
    }
    for (; j < c; j++) {
        float cf = scoef[wid][j];
        float2 v = __ldg(y2 + (size_t)scol[wid][j] * 32 + lane);
        a0.x += cf * v.x; a0.y += cf * v.y;
    }
    a0.x += a1.x + a2.x + a3.x;
    a0.y += a1.y + a2.y + a3.y;
    sres[wid][2 * lane] = a0.x;
    sres[wid][2 * lane + 1] = a0.y;
    __syncthreads();

    // coalesced write: out[(a+1)*64+e][base..base+7], 32B chunks
    for (int i = tid; i < 8 * EE; i += 256) {
        int e = i >> 3;
        int r = i & 7;
        out[(size_t)((a + 1) * EE + e) * NN + base + r] = sres[r][e];
    }
}

extern "C" void kernel_launch(void* const* d_in, const int* in_sizes, int n_in,
                              void* d_out, int out_size) {
    const float* feat   = (const float*)d_in[0];
    const float* geo    = (const float*)d_in[1];
    const float* fwd    = (const float*)d_in[2];
    const float* bwd    = (const float*)d_in[3];
    const float* weight = (const float*)d_in[4];
    const float* Wf  = (const float*)d_in[5];
    const float* af1 = (const float*)d_in[6];
    const float* af2 = (const float*)d_in[7];
    const float* Wb  = (const float*)d_in[8];
    const float* ab1 = (const float*)d_in[9];
    const float* ab2 = (const float*)d_in[10];
    const float* Wg  = (const float*)d_in[11];
    const float* ag1 = (const float*)d_in[12];
    const float* ag2 = (const float*)d_in[13];
    float* out = (float*)d_out;

    init_kernel<<<7, 768>>>(Wf, af1, af2, Wb, ab1, ab2, Wg, ag1, ag2);
    proj_sv_kernel<<<NN / 8, 256>>>(feat);
    y_kernel<<<NN / 32, dim3(32, 8)>>>(feat, weight, out);
    scan_kernel<<<dim3(NN, 3), 256>>>(fwd, bwd, geo);
    stats_bwd_kernel<<<NN / 8, 256>>>();
    aggE_kernel<<<dim3(NN / 8, 3), 256>>>(out);
}

// round 5
// speedup vs baseline: 1.8992x; 1.0375x over previous
#include <cuda_runtime.h>
#include <cuda_fp16.h>

#define NN 4096
#define FF 128
#define EE 64
#define MAXD 192
#define LRALPHA 0.2f
#define FULLW 0xffffffffu

// ---- scratch (device globals) ----
__device__ float  g_wa[6][FF];
__device__ float  g_sv[6][NN];          // s1_fwd, u_fwd, s1_bwd, u_bwd, s1_geo, u_geo
__device__ float  g_s2[3][NN];
__device__ float4 g_pack[NN];           // bwd per-source: {s1, m, 1/Z, _}
__device__ int    g_cnt[3][NN];
__device__ int    g_rowlist[3][NN * MAXD];
__device__ int    g_colcnt[NN];
__device__ int    g_collist[NN * MAXD];
__device__ __half g_yth[NN * EE];       // fp16 copy of (weight @ t^T), [n][e]

__device__ __forceinline__ float lrelu(float x) {
    return x > 0.f ? x : LRALPHA * x;
}

// ---- kernel 0: y = weight @ t^T -> out part 0 (fp32) + g_yth (fp16, coalesced)
//      also: wa[k] = W @ a (block 0), zero colcnt (blocks 0..15) ----
__global__ void y_kernel(const float* __restrict__ t,
                         const float* __restrict__ weight,
                         const float* __restrict__ Wf, const float* __restrict__ af1, const float* __restrict__ af2,
                         const float* __restrict__ Wb, const float* __restrict__ ab1, const float* __restrict__ ab2,
                         const float* __restrict__ Wg, const float* __restrict__ ag1, const float* __restrict__ ag2,
                         float* __restrict__ out) {
    int n0 = blockIdx.x * 32;
    __shared__ float Gs[FF][32];
    __shared__ float Ws[EE][FF];
    __shared__ __align__(16) __half Hs[32][EE];

    int tid = threadIdx.y * 32 + threadIdx.x;   // 256
    for (int i = tid; i < 32 * FF; i += 256) {
        int nn = i & 31;
        int f = i >> 5;
        Gs[f][nn] = t[(size_t)(n0 + nn) * FF + f];
    }
    for (int i = tid; i < EE * FF; i += 256)
        Ws[i / FF][i % FF] = weight[i];
    __syncthreads();

    int tx = threadIdx.x;
    int ty = threadIdx.y;
    float acc[8] = {0.f, 0.f, 0.f, 0.f, 0.f, 0.f, 0.f, 0.f};
    for (int f = 0; f < FF; f++) {
        float gv = Gs[f][tx];
#pragma unroll
        for (int eg = 0; eg < 8; eg++)
            acc[eg] += Ws[ty * 8 + eg][f] * gv;
    }
#pragma unroll
    for (int eg = 0; eg < 8; eg++) {
        int e = ty * 8 + eg;
        out[(size_t)e * NN + n0 + tx] = acc[eg];
        Hs[tx][e] = __float2half_rn(acc[eg]);
    }
    __syncthreads();
    // coalesced fp16 table store: 32 rows x 128 B
    {
        int nn = tid >> 3;
        int ch = tid & 7;
        reinterpret_cast<uint4*>(&g_yth[(size_t)(n0 + nn) * EE])[ch] =
            reinterpret_cast<const uint4*>(Hs[nn])[ch];
    }
    // side jobs
    if (blockIdx.x < 16) {
        int i = blockIdx.x * 256 + tid;
        g_colcnt[i] = 0;
    }
    if (blockIdx.x == 0) {
        for (int i = tid; i < 6 * FF; i += 256) {
            int k = i >> 7;
            int f = i & 127;
            const float* W = (k < 2) ? Wf : (k < 4) ? Wb : Wg;
            const float* a = (k == 0) ? af1 : (k == 1) ? af2 : (k == 2) ? ab1 :
                             (k == 3) ? ab2 : (k == 4) ? ag1 : ag2;
            float s = 0.f;
#pragma unroll
            for (int e = 0; e < EE; e++) s += W[f * EE + e] * a[e];
            g_wa[k][f] = s;
        }
    }
}

// ---- kernel 1: sv[k][n] = t[n,:] . wa[k]; warp per row ----
__global__ void proj_sv_kernel(const float* __restrict__ t) {
    __shared__ float swa[6][FF];
    int tid = threadIdx.x;            // 256
    for (int i = tid; i < 6 * FF; i += 256)
        ((float*)swa)[i] = ((const float*)g_wa)[i];
    __syncthreads();
    int wid = tid >> 5, lane = tid & 31;
    int row = blockIdx.x * 8 + wid;
    const float4* t4 = reinterpret_cast<const float4*>(t + (size_t)row * FF);
    float4 v = __ldg(t4 + lane);
    float acc[6];
#pragma unroll
    for (int k = 0; k < 6; k++) {
        float4 w = reinterpret_cast<const float4*>(swa[k])[lane];
        acc[k] = v.x * w.x + v.y * w.y + v.z * w.z + v.w * w.w;
    }
#pragma unroll
    for (int k = 0; k < 6; k++) {
        float s = acc[k];
#pragma unroll
        for (int o = 16; o; o >>= 1) s += __shfl_xor_sync(FULLW, s, o);
        if (lane == 0) g_sv[k][row] = s;
    }
}

// ---- kernel 2: adjacency scan. 128 threads/row, 8 uint4 per thread (MLP=8).
// Values are exactly 0.0f or 1.0f -> bit29 extraction, branch-free mask. ----
__global__ void scan_kernel(const float* __restrict__ fwd,
                            const float* __restrict__ bwd,
                            const float* __restrict__ geo) {
    int a = blockIdx.y;
    int row = blockIdx.x;
    const float* adj = (a == 0) ? fwd : (a == 1) ? bwd : geo;
    const uint4* rp = reinterpret_cast<const uint4*>(adj + (size_t)row * NN);

    __shared__ int scnt;
    __shared__ float sdot;
    if (threadIdx.x == 0) { scnt = 0; sdot = 0.f; }
    __syncthreads();

    const float* u = g_sv[2 * a + 1];
    int* list = &g_rowlist[a][(size_t)row * MAXD];
    int t = threadIdx.x;              // 0..127
    int lane = t & 31;

    uint4 v[8];
#pragma unroll
    for (int k = 0; k < 8; k++) v[k] = __ldg(rp + t + k * 128);

    // 1.0f = 0x3F800000 -> (>>29)&1 == 1 ; 0.0f -> 0
    unsigned mask = 0;
#pragma unroll
    for (int k = 0; k < 8; k++) {
        mask |= ((v[k].x >> 29) & 1u) << (4 * k + 0);
        mask |= ((v[k].y >> 29) & 1u) << (4 * k + 1);
        mask |= ((v[k].z >> 29) & 1u) << (4 * k + 2);
        mask |= ((v[k].w >> 29) & 1u) << (4 * k + 3);
    }

    int cnt = __popc(mask);
    int incl = cnt;
#pragma unroll
    for (int d = 1; d < 32; d <<= 1) {
        int nb = __shfl_up_sync(FULLW, incl, d);
        if (lane >= d) incl += nb;
    }
    int warpTotal = __shfl_sync(FULLW, incl, 31);
    int excl = incl - cnt;
    int wb = 0;
    if (lane == 0 && warpTotal) wb = atomicAdd(&scnt, warpTotal);
    wb = __shfl_sync(FULLW, wb, 0);
    int base = wb + excl;

    float dot = 0.f;
    unsigned m = mask;
    while (m) {
        int b = __ffs(m) - 1;
        m &= m - 1;
        int col = (t << 2) + ((b >> 2) << 9) + (b & 3);
        if (base < MAXD) list[base] = col;
        base++;
        dot += u[col];
        if (a == 1) {
            int pc = atomicAdd(&g_colcnt[col], 1);
            if (pc < MAXD) g_collist[(size_t)col * MAXD + pc] = row;
        }
    }

#pragma unroll
    for (int o = 16; o; o >>= 1) dot += __shfl_xor_sync(FULLW, dot, o);
    if (lane == 0) atomicAdd(&sdot, dot);
    __syncthreads();

    if (threadIdx.x == 0) {
        int c = scnt;
        g_cnt[a][row] = min(c, MAXD);
        float deg = (c < 1) ? 1.f : (float)c;
        g_s2[a][row] = sdot / deg;
    }
}

// ---- kernel 3: softmax stats for BACKWARD rows -> packed float4 ----
__global__ void stats_bwd_kernel() {
    int gw = (blockIdx.x * blockDim.x + threadIdx.x) >> 5;
    int lane = threadIdx.x & 31;
    if (gw >= NN) return;
    int row = gw;
    int c = g_cnt[1][row];
    const int* list = &g_rowlist[1][(size_t)row * MAXD];
    float s1 = g_sv[2][row];
    const float* s2 = g_s2[1];

    float vals[MAXD / 32];
    float mx = -3.0e38f;
#pragma unroll
    for (int k = 0; k < MAXD / 32; k++) {
        int j = lane + k * 32;
        float v = (j < c) ? lrelu(s1 + s2[list[j]]) : -3.0e38f;
        vals[k] = v;
        mx = fmaxf(mx, v);
    }
#pragma unroll
    for (int o = 16; o; o >>= 1) mx = fmaxf(mx, __shfl_xor_sync(FULLW, mx, o));

    float z = 0.f;
#pragma unroll
    for (int k = 0; k < MAXD / 32; k++) {
        int j = lane + k * 32;
        if (j < c) z += __expf(vals[k] - mx);
    }
#pragma unroll
    for (int o = 16; o; o >>= 1) z += __shfl_xor_sync(FULLW, z, o);

    if (lane == 0) g_pack[row] = make_float4(s1, mx, 1.f / z, 0.f);
}

// ---- kernel 4: E-domain aggregation, fp16 gather (half2 per lane per edge) ----
__global__ void aggE_kernel(float* __restrict__ out) {
    int a = blockIdx.y;
    int base = blockIdx.x * 8;
    int tid = threadIdx.x;            // 256
    int wid = tid >> 5, lane = tid & 31;
    int row = base + wid;

    __shared__ float scoef[8][MAXD];
    __shared__ int   scol[8][MAXD];
    __shared__ float sres[8][EE];

    int c;
    const int* list;
    if (a == 1) {
        c = min(g_colcnt[row], MAXD);
        list = &g_collist[(size_t)row * MAXD];
    } else {
        c = g_cnt[a][row];
        list = &g_rowlist[a][(size_t)row * MAXD];
    }

    if (a == 1) {
        float s2r = g_s2[1][row];
#pragma unroll
        for (int k = 0; k < MAXD / 32; k++) {
            int j = lane + k * 32;
            if (j < c) {
                int col = list[j];
                float4 p = __ldg(&g_pack[col]);
                float x = lrelu(p.x + s2r);
                scoef[wid][j] = __expf(x - p.y) * p.z;
                scol[wid][j] = col;
            }
        }
    } else {
        float s1 = g_sv[2 * a][row];
        const float* s2 = g_s2[a];
        float vals[MAXD / 32];
        int cols[MAXD / 32];
        float mx = -3.0e38f;
#pragma unroll
        for (int k = 0; k < MAXD / 32; k++) {
            int j = lane + k * 32;
            if (j < c) {
                int col = list[j];
                cols[k] = col;
                float x = lrelu(s1 + s2[col]);
                vals[k] = x;
                mx = fmaxf(mx, x);
            } else vals[k] = -3.0e38f;
        }
#pragma unroll
        for (int o = 16; o; o >>= 1) mx = fmaxf(mx, __shfl_xor_sync(FULLW, mx, o));
        float z = 0.f;
#pragma unroll
        for (int k = 0; k < MAXD / 32; k++) {
            int j = lane + k * 32;
            if (j < c) { float e = __expf(vals[k] - mx); vals[k] = e; z += e; }
        }
#pragma unroll
        for (int o = 16; o; o >>= 1) z += __shfl_xor_sync(FULLW, z, o);
        float inv = 1.f / z;
#pragma unroll
        for (int k = 0; k < MAXD / 32; k++) {
            int j = lane + k * 32;
            if (j < c) { scoef[wid][j] = vals[k] * inv; scol[wid][j] = cols[k]; }
        }
    }
    __syncwarp();

    // gather: lane covers e = {2*lane, 2*lane+1}; one half2 (4B) per edge per lane
    const __half2* y2 = reinterpret_cast<const __half2*>(g_yth);
    float2 a0 = {0.f, 0.f}, a1 = {0.f, 0.f}, a2 = {0.f, 0.f}, a3 = {0.f, 0.f};
    int j = 0;
    for (; j + 4 <= c; j += 4) {
        float c0 = scoef[wid][j + 0]; int l0 = scol[wid][j + 0];
        float c1 = scoef[wid][j + 1]; int l1 = scol[wid][j + 1];
        float c2 = scoef[wid][j + 2]; int l2 = scol[wid][j + 2];
        float c3 = scoef[wid][j + 3]; int l3 = scol[wid][j + 3];
        float2 v0 = __half22float2(__ldg(y2 + (size_t)l0 * 32 + lane));
        float2 v1 = __half22float2(__ldg(y2 + (size_t)l1 * 32 + lane));
        float2 v2 = __half22float2(__ldg(y2 + (size_t)l2 * 32 + lane));
        float2 v3 = __half22float2(__ldg(y2 + (size_t)l3 * 32 + lane));
        a0.x += c0 * v0.x; a0.y += c0 * v0.y;
        a1.x += c1 * v1.x; a1.y += c1 * v1.y;
        a2.x += c2 * v2.x; a2.y += c2 * v2.y;
        a3.x += c3 * v3.x; a3.y += c3 * v3.y;
    }
    for (; j < c; j++) {
        float cf = scoef[wid][j];
        float2 v = __half22float2(__ldg(y2 + (size_t)scol[wid][j] * 32 + lane));
        a0.x += cf * v.x; a0.y += cf * v.y;
    }
    a0.x += a1.x + a2.x + a3.x;
    a0.y += a1.y + a2.y + a3.y;
    sres[wid][2 * lane] = a0.x;
    sres[wid][2 * lane + 1] = a0.y;
    __syncthreads();

    for (int i = tid; i < 8 * EE; i += 256) {
        int e = i >> 3;
        int r = i & 7;
        out[(size_t)((a + 1) * EE + e) * NN + base + r] = sres[r][e];
    }
}

extern "C" void kernel_launch(void* const* d_in, const int* in_sizes, int n_in,
                              void* d_out, int out_size) {
    const float* feat   = (const float*)d_in[0];
    const float* geo    = (const float*)d_in[1];
    const float* fwd    = (const float*)d_in[2];
    const float* bwd    = (const float*)d_in[3];
    const float* weight = (const float*)d_in[4];
    const float* Wf  = (const float*)d_in[5];
    const float* af1 = (const float*)d_in[6];
    const float* af2 = (const float*)d_in[7];
    const float* Wb  = (const float*)d_in[8];
    const float* ab1 = (const float*)d_in[9];
    const float* ab2 = (const float*)d_in[10];
    const float* Wg  = (const float*)d_in[11];
    const float* ag1 = (const float*)d_in[12];
    const float* ag2 = (const float*)d_in[13];
    float* out = (float*)d_out;

    y_kernel<<<NN / 32, dim3(32, 8)>>>(feat, weight, Wf, af1, af2, Wb, ab1, ab2, Wg, ag1, ag2, out);
    proj_sv_kernel<<<NN / 8, 256>>>(feat);
    scan_kernel<<<dim3(NN, 3), 128>>>(fwd, bwd, geo);
    stats_bwd_kernel<<<NN / 8, 256>>>();
    aggE_kernel<<<dim3(NN / 8, 3), 256>>>(out);
}

// round 6
// speedup vs baseline: 2.2008x; 1.1588x over previous
#include <cuda_runtime.h>
#include <cuda_fp16.h>

#define NN 4096
#define FF 128
#define EE 64
#define MAXD 192
#define LRALPHA 0.2f
#define FULLW 0xffffffffu

// ---- scratch (device globals) ----
__device__ float  g_wa[6][FF];
__device__ float  g_sv[6][NN];          // s1_fwd, u_fwd, s1_bwd, u_bwd, s1_geo, u_geo
__device__ float  g_s2[3][NN];
__device__ float4 g_pack[NN];           // bwd per-source: {s1, m, 1/Z, _}
__device__ int    g_cnt[3][NN];
__device__ int    g_rowlist[3][NN * MAXD];
__device__ int    g_colcnt[NN];
__device__ int    g_collist[NN * MAXD];
__device__ __half g_yth[NN * EE];       // fp16 copy of (weight @ t^T), [n][e]

__device__ __forceinline__ float lrelu(float x) {
    return x > 0.f ? x : LRALPHA * x;
}

// ---- kernel A0: blocks 0..15 zero colcnt; block 16 computes wa[k] = W @ a ----
__global__ void init_kernel(const float* __restrict__ Wf, const float* __restrict__ af1, const float* __restrict__ af2,
                            const float* __restrict__ Wb, const float* __restrict__ ab1, const float* __restrict__ ab2,
                            const float* __restrict__ Wg, const float* __restrict__ ag1, const float* __restrict__ ag2) {
    int tid = threadIdx.x;            // 256
    if (blockIdx.x < 16) {
        g_colcnt[blockIdx.x * 256 + tid] = 0;
        return;
    }
    for (int i = tid; i < 6 * FF; i += 256) {
        int k = i >> 7;
        int f = i & 127;
        const float* W = (k < 2) ? Wf : (k < 4) ? Wb : Wg;
        const float* a = (k == 0) ? af1 : (k == 1) ? af2 : (k == 2) ? ab1 :
                         (k == 3) ? ab2 : (k == 4) ? ag1 : ag2;
        float s = 0.f;
#pragma unroll
        for (int e = 0; e < EE; e++) s += W[f * EE + e] * a[e];
        g_wa[k][f] = s;
    }
}

// ---- kernel A1: sv[k][n] = t[n,:] . wa[k]; warp per row ----
__global__ void proj_sv_kernel(const float* __restrict__ t) {
    __shared__ float swa[6][FF];
    int tid = threadIdx.x;            // 256
    for (int i = tid; i < 6 * FF; i += 256)
        ((float*)swa)[i] = ((const float*)g_wa)[i];
    __syncthreads();
    int wid = tid >> 5, lane = tid & 31;
    int row = blockIdx.x * 8 + wid;
    const float4* t4 = reinterpret_cast<const float4*>(t + (size_t)row * FF);
    float4 v = __ldg(t4 + lane);
    float acc[6];
#pragma unroll
    for (int k = 0; k < 6; k++) {
        float4 w = reinterpret_cast<const float4*>(swa[k])[lane];
        acc[k] = v.x * w.x + v.y * w.y + v.z * w.z + v.w * w.w;
    }
#pragma unroll
    for (int k = 0; k < 6; k++) {
        float s = acc[k];
#pragma unroll
        for (int o = 16; o; o >>= 1) s += __shfl_xor_sync(FULLW, s, o);
        if (lane == 0) g_sv[k][row] = s;
    }
}

// ---- kernel C0 (parallel stream): y = weight @ t^T -> out part 0 + fp16 table ----
__global__ void y_kernel(const float* __restrict__ t,
                         const float* __restrict__ weight,
                         float* __restrict__ out) {
    int n0 = blockIdx.x * 32;
    __shared__ float Gs[FF][32];
    __shared__ float Ws[EE][FF];
    __shared__ __align__(16) __half Hs[32][EE];

    int tid = threadIdx.y * 32 + threadIdx.x;   // 256
    for (int i = tid; i < 32 * FF; i += 256) {
        int nn = i & 31;
        int f = i >> 5;
        Gs[f][nn] = t[(size_t)(n0 + nn) * FF + f];
    }
    for (int i = tid; i < EE * FF; i += 256)
        Ws[i / FF][i % FF] = weight[i];
    __syncthreads();

    int tx = threadIdx.x;
    int ty = threadIdx.y;
    float acc[8] = {0.f, 0.f, 0.f, 0.f, 0.f, 0.f, 0.f, 0.f};
    for (int f = 0; f < FF; f++) {
        float gv = Gs[f][tx];
#pragma unroll
        for (int eg = 0; eg < 8; eg++)
            acc[eg] += Ws[ty * 8 + eg][f] * gv;
    }
#pragma unroll
    for (int eg = 0; eg < 8; eg++) {
        int e = ty * 8 + eg;
        out[(size_t)e * NN + n0 + tx] = acc[eg];
        Hs[tx][e] = __float2half_rn(acc[eg]);
    }
    __syncthreads();
    {
        int nn = tid >> 3;
        int ch = tid & 7;
        reinterpret_cast<uint4*>(&g_yth[(size_t)(n0 + nn) * EE])[ch] =
            reinterpret_cast<const uint4*>(Hs[nn])[ch];
    }
}

// ---- kernel A2: adjacency scan. 128 threads/row, 8 uint4 per thread. ----
__global__ void scan_kernel(const float* __restrict__ fwd,
                            const float* __restrict__ bwd,
                            const float* __restrict__ geo) {
    int a = blockIdx.y;
    int row = blockIdx.x;
    const float* adj = (a == 0) ? fwd : (a == 1) ? bwd : geo;
    const uint4* rp = reinterpret_cast<const uint4*>(adj + (size_t)row * NN);

    __shared__ int scnt;
    __shared__ float sdot;
    if (threadIdx.x == 0) { scnt = 0; sdot = 0.f; }
    __syncthreads();

    const float* u = g_sv[2 * a + 1];
    int* list = &g_rowlist[a][(size_t)row * MAXD];
    int t = threadIdx.x;              // 0..127
    int lane = t & 31;

    uint4 v[8];
#pragma unroll
    for (int k = 0; k < 8; k++) v[k] = __ldg(rp + t + k * 128);

    // 1.0f = 0x3F800000 -> (>>29)&1 == 1 ; 0.0f -> 0
    unsigned mask = 0;
#pragma unroll
    for (int k = 0; k < 8; k++) {
        mask |= ((v[k].x >> 29) & 1u) << (4 * k + 0);
        mask |= ((v[k].y >> 29) & 1u) << (4 * k + 1);
        mask |= ((v[k].z >> 29) & 1u) << (4 * k + 2);
        mask |= ((v[k].w >> 29) & 1u) << (4 * k + 3);
    }

    int cnt = __popc(mask);
    int incl = cnt;
#pragma unroll
    for (int d = 1; d < 32; d <<= 1) {
        int nb = __shfl_up_sync(FULLW, incl, d);
        if (lane >= d) incl += nb;
    }
    int warpTotal = __shfl_sync(FULLW, incl, 31);
    int excl = incl - cnt;
    int wb = 0;
    if (lane == 0 && warpTotal) wb = atomicAdd(&scnt, warpTotal);
    wb = __shfl_sync(FULLW, wb, 0);
    int base = wb + excl;

    float dot = 0.f;
    unsigned m = mask;
    while (m) {
        int b = __ffs(m) - 1;
        m &= m - 1;
        int col = (t << 2) + ((b >> 2) << 9) + (b & 3);
        if (base < MAXD) list[base] = col;
        base++;
        dot += u[col];
        if (a == 1) {
            int pc = atomicAdd(&g_colcnt[col], 1);
            if (pc < MAXD) g_collist[(size_t)col * MAXD + pc] = row;
        }
    }

#pragma unroll
    for (int o = 16; o; o >>= 1) dot += __shfl_xor_sync(FULLW, dot, o);
    if (lane == 0) atomicAdd(&sdot, dot);
    __syncthreads();

    if (threadIdx.x == 0) {
        int c = scnt;
        g_cnt[a][row] = min(c, MAXD);
        float deg = (c < 1) ? 1.f : (float)c;
        g_s2[a][row] = sdot / deg;
    }
}

// ---- kernel B0: softmax stats for BACKWARD rows -> packed float4 ----
__global__ void stats_bwd_kernel() {
    int gw = (blockIdx.x * blockDim.x + threadIdx.x) >> 5;
    int lane = threadIdx.x & 31;
    if (gw >= NN) return;
    int row = gw;
    int c = g_cnt[1][row];
    const int* list = &g_rowlist[1][(size_t)row * MAXD];
    float s1 = g_sv[2][row];
    const float* s2 = g_s2[1];

    float vals[MAXD / 32];
    float mx = -3.0e38f;
#pragma unroll
    for (int k = 0; k < MAXD / 32; k++) {
        int j = lane + k * 32;
        float v = (j < c) ? lrelu(s1 + s2[list[j]]) : -3.0e38f;
        vals[k] = v;
        mx = fmaxf(mx, v);
    }
#pragma unroll
    for (int o = 16; o; o >>= 1) mx = fmaxf(mx, __shfl_xor_sync(FULLW, mx, o));

    float z = 0.f;
#pragma unroll
    for (int k = 0; k < MAXD / 32; k++) {
        int j = lane + k * 32;
        if (j < c) z += __expf(vals[k] - mx);
    }
#pragma unroll
    for (int o = 16; o; o >>= 1) z += __shfl_xor_sync(FULLW, z, o);

    if (lane == 0) g_pack[row] = make_float4(s1, mx, 1.f / z, 0.f);
}

// ---- shared gather epilogue: warp-level fp16 gather over edge list in smem ----
__device__ __forceinline__ void gather_store(const float* scoef, const int* scol, int c,
                                             int wid, int lane, int tid, int base, int part,
                                             float (*sres)[EE], float* out) {
    const __half2* y2 = reinterpret_cast<const __half2*>(g_yth);
    float2 a0 = {0.f, 0.f}, a1 = {0.f, 0.f}, a2 = {0.f, 0.f}, a3 = {0.f, 0.f};
    int j = 0;
    for (; j + 4 <= c; j += 4) {
        float c0 = scoef[j + 0]; int l0 = scol[j + 0];
        float c1 = scoef[j + 1]; int l1 = scol[j + 1];
        float c2 = scoef[j + 2]; int l2 = scol[j + 2];
        float c3 = scoef[j + 3]; int l3 = scol[j + 3];
        float2 v0 = __half22float2(__ldg(y2 + (size_t)l0 * 32 + lane));
        float2 v1 = __half22float2(__ldg(y2 + (size_t)l1 * 32 + lane));
        float2 v2 = __half22float2(__ldg(y2 + (size_t)l2 * 32 + lane));
        float2 v3 = __half22float2(__ldg(y2 + (size_t)l3 * 32 + lane));
        a0.x += c0 * v0.x; a0.y += c0 * v0.y;
        a1.x += c1 * v1.x; a1.y += c1 * v1.y;
        a2.x += c2 * v2.x; a2.y += c2 * v2.y;
        a3.x += c3 * v3.x; a3.y += c3 * v3.y;
    }
    for (; j < c; j++) {
        float cf = scoef[j];
        float2 v = __half22float2(__ldg(y2 + (size_t)scol[j] * 32 + lane));
        a0.x += cf * v.x; a0.y += cf * v.y;
    }
    a0.x += a1.x + a2.x + a3.x;
    a0.y += a1.y + a2.y + a3.y;
    sres[wid][2 * lane] = a0.x;
    sres[wid][2 * lane + 1] = a0.y;
    __syncthreads();

    for (int i = tid; i < 8 * EE; i += 256) {
        int e = i >> 3;
        int r = i & 7;
        out[(size_t)(part * EE + e) * NN + base + r] = sres[r][e];
    }
}

// ---- kernel A3: fwd+geo aggregation (fused row softmax), warp per row ----
__global__ void aggE_fg_kernel(float* __restrict__ out) {
    int aa = (blockIdx.y == 0) ? 0 : 2;   // adjacency index
    int base = blockIdx.x * 8;
    int tid = threadIdx.x;                // 256
    int wid = tid >> 5, lane = tid & 31;
    int row = base + wid;

    __shared__ float scoef[8][MAXD];
    __shared__ int   scol[8][MAXD];
    __shared__ float sres[8][EE];

    int c = g_cnt[aa][row];
    const int* list = &g_rowlist[aa][(size_t)row * MAXD];

    float s1 = g_sv[2 * aa][row];
    const float* s2 = g_s2[aa];
    float vals[MAXD / 32];
    int cols[MAXD / 32];
    float mx = -3.0e38f;
#pragma unroll
    for (int k = 0; k < MAXD / 32; k++) {
        int j = lane + k * 32;
        if (j < c) {
            int col = list[j];
            cols[k] = col;
            float x = lrelu(s1 + s2[col]);
            vals[k] = x;
            mx = fmaxf(mx, x);
        } else vals[k] = -3.0e38f;
    }
#pragma unroll
    for (int o = 16; o; o >>= 1) mx = fmaxf(mx, __shfl_xor_sync(FULLW, mx, o));
    float z = 0.f;
#pragma unroll
    for (int k = 0; k < MAXD / 32; k++) {
        int j = lane + k * 32;
        if (j < c) { float e = __expf(vals[k] - mx); vals[k] = e; z += e; }
    }
#pragma unroll
    for (int o = 16; o; o >>= 1) z += __shfl_xor_sync(FULLW, z, o);
    float inv = 1.f / z;
#pragma unroll
    for (int k = 0; k < MAXD / 32; k++) {
        int j = lane + k * 32;
        if (j < c) { scoef[wid][j] = vals[k] * inv; scol[wid][j] = cols[k]; }
    }
    __syncwarp();

    gather_store(scoef[wid], scol[wid], c, wid, lane, tid, base, aa + 1, sres, out);
}

// ---- kernel B1: bwd aggregation via CSC + packed stats ----
__global__ void aggE_bwd_kernel(float* __restrict__ out) {
    int base = blockIdx.x * 8;
    int tid = threadIdx.x;                // 256
    int wid = tid >> 5, lane = tid & 31;
    int row = base + wid;

    __shared__ float scoef[8][MAXD];
    __shared__ int   scol[8][MAXD];
    __shared__ float sres[8][EE];

    int c = min(g_colcnt[row], MAXD);
    const int* list = &g_collist[(size_t)row * MAXD];
    float s2r = g_s2[1][row];
#pragma unroll
    for (int k = 0; k < MAXD / 32; k++) {
        int j = lane + k * 32;
        if (j < c) {
            int col = list[j];
            float4 p = __ldg(&g_pack[col]);
            float x = lrelu(p.x + s2r);
            scoef[wid][j] = __expf(x - p.y) * p.z;
            scol[wid][j] = col;
        }
    }
    __syncwarp();

    gather_store(scoef[wid], scol[wid], c, wid, lane, tid, base, 2, sres, out);
}

extern "C" void kernel_launch(void* const* d_in, const int* in_sizes, int n_in,
                              void* d_out, int out_size) {
    const float* feat   = (const float*)d_in[0];
    const float* geo    = (const float*)d_in[1];
    const float* fwd    = (const float*)d_in[2];
    const float* bwd    = (const float*)d_in[3];
    const float* weight = (const float*)d_in[4];
    const float* Wf  = (const float*)d_in[5];
    const float* af1 = (const float*)d_in[6];
    const float* af2 = (const float*)d_in[7];
    const float* Wb  = (const float*)d_in[8];
    const float* ab1 = (const float*)d_in[9];
    const float* ab2 = (const float*)d_in[10];
    const float* Wg  = (const float*)d_in[11];
    const float* ag1 = (const float*)d_in[12];
    const float* ag2 = (const float*)d_in[13];
    float* out = (float*)d_out;

    // lazily-created side streams / events (host resources only; identical work per call)
    static cudaStream_t sB = [] { cudaStream_t s; cudaStreamCreateWithFlags(&s, cudaStreamNonBlocking); return s; }();
    static cudaStream_t sC = [] { cudaStream_t s; cudaStreamCreateWithFlags(&s, cudaStreamNonBlocking); return s; }();
    static cudaEvent_t evRoot = [] { cudaEvent_t e; cudaEventCreateWithFlags(&e, cudaEventDisableTiming); return e; }();
    static cudaEvent_t evY    = [] { cudaEvent_t e; cudaEventCreateWithFlags(&e, cudaEventDisableTiming); return e; }();
    static cudaEvent_t evScan = [] { cudaEvent_t e; cudaEventCreateWithFlags(&e, cudaEventDisableTiming); return e; }();
    static cudaEvent_t evB    = [] { cudaEvent_t e; cudaEventCreateWithFlags(&e, cudaEventDisableTiming); return e; }();

    // fork stream C off the main (captured) stream
    cudaEventRecord(evRoot, 0);
    cudaStreamWaitEvent(sC, evRoot, 0);

    // main stream: init -> proj -> scan
    init_kernel<<<17, 256>>>(Wf, af1, af2, Wb, ab1, ab2, Wg, ag1, ag2);
    proj_sv_kernel<<<NN / 8, 256>>>(feat);

    // stream C: y (independent of everything above)
    y_kernel<<<NN / 32, dim3(32, 8), 0, sC>>>(feat, weight, out);
    cudaEventRecord(evY, sC);

    scan_kernel<<<dim3(NN, 3), 128>>>(fwd, bwd, geo);
    cudaEventRecord(evScan, 0);

    // stream B: stats_bwd -> aggE_bwd (needs scan + y)
    cudaStreamWaitEvent(sB, evScan, 0);
    cudaStreamWaitEvent(sB, evY, 0);
    stats_bwd_kernel<<<NN / 8, 256, 0, sB>>>();
    aggE_bwd_kernel<<<NN / 8, 256, 0, sB>>>(out);
    cudaEventRecord(evB, sB);

    // main stream: fwd+geo aggregation (needs scan + y)
    cudaStreamWaitEvent(0, evY, 0);
    aggE_fg_kernel<<<dim3(NN / 8, 2), 256>>>(out);

    // join
    cudaStreamWaitEvent(0, evB, 0);
}